// round 13
// baseline (speedup 1.0000x reference)
#include <cuda_runtime.h>
#include <math.h>

#define NN   50000
#define NPAD 50048                 // 391 * 128
#define EE   400000
#define ETOT (NN + EE)
#define HID  128

// ---------------- scratch (device globals; zero-initialized at load) ----------------
__device__ __align__(16) float    g_h[NN * HID];        // node features
__device__ __align__(16) float    g_xlr[NN * 2 * HID];  // [xl | xr] per row
__device__ __align__(16) unsigned g_ap[NPAD * 256];     // packed tf32 A: per row 64 uint4 (h,h,l,l)
__device__ __align__(16) unsigned g_bfp[4 * 65536];     // packed tf32 B frags, all 4 layers
__device__ float  g_easum[NN * 4];
__device__ int    g_deg[NN];
__device__ int    g_fill[NN];
__device__ int    g_rowptr[NN + 1];
__device__ int    g_src[EE];
__device__ int    g_dst[EE];
__device__ int    g_csrc[ETOT];
__device__ float4 g_cea4[ETOT];
__device__ float  g_gamma[HID];
__device__ float  g_beta[HID];
__device__ float  g_mask[NN];
__device__ int    g_is64;
__device__ int    g_mtype;

__device__ __forceinline__ float gelu_exact(float x) {
    return 0.5f * x * (1.0f + erff(x * 0.70710678118654752440f));
}

__device__ __forceinline__ unsigned f2tf32(float v) {
    unsigned r;
    asm("cvt.rna.tf32.f32 %0, %1;" : "=r"(r) : "f"(v));
    return r;
}

// write packed tf32 hi/lo for (row, col) into g_ap
__device__ __forceinline__ void store_ap(int row, int col, float v) {
    unsigned h = f2tf32(v);
    unsigned l = f2tf32(v - __uint_as_float(h));
    int ks = col >> 3, tg = col & 3, s = (col >> 2) & 1;
    int base = row * 256 + ks * 16 + tg * 4;
    g_ap[base + s]     = h;
    g_ap[base + 2 + s] = l;
}

__device__ __forceinline__ void mma8(float c[4],
                                     unsigned a0, unsigned a1, unsigned a2, unsigned a3,
                                     unsigned b0, unsigned b1) {
    asm volatile("mma.sync.aligned.m16n8k8.row.col.f32.tf32.tf32.f32 "
                 "{%0,%1,%2,%3}, {%4,%5,%6,%7}, {%8,%9}, {%0,%1,%2,%3};"
                 : "+f"(c[0]), "+f"(c[1]), "+f"(c[2]), "+f"(c[3])
                 : "r"(a0), "r"(a1), "r"(a2), "r"(a3), "r"(b0), "r"(b1));
}

// ---------------- encoder: h = gelu(ln(x @ W + b)); writes g_h AND packed tf32 ----------------
__global__ void k_enc(const float* __restrict__ x, const float* __restrict__ W,
                      const float* __restrict__ b, const float* __restrict__ lg,
                      const float* __restrict__ lb) {
    int v = blockIdx.x;
    int j = threadIdx.x;                       // 128 threads; thread j = column j
    __shared__ float xs[8];
    __shared__ float r1[4], r2[4];
    if (j < 6) xs[j] = x[v * 6 + j];
    __syncthreads();
    float s = b[j];
#pragma unroll
    for (int k = 0; k < 6; k++) s += xs[k] * W[k * HID + j];
    float t1 = s, t2 = s * s;
#pragma unroll
    for (int o = 16; o; o >>= 1) {
        t1 += __shfl_xor_sync(0xffffffffu, t1, o);
        t2 += __shfl_xor_sync(0xffffffffu, t2, o);
    }
    int lane = j & 31, w = j >> 5;
    if (lane == 0) { r1[w] = t1; r2[w] = t2; }
    __syncthreads();
    float S1 = r1[0] + r1[1] + r1[2] + r1[3];
    float S2 = r2[0] + r2[1] + r2[2] + r2[3];
    float mean = S1 * (1.0f / HID);
    float var  = S2 * (1.0f / HID) - mean * mean;
    float y = (s - mean) * rsqrtf(var + 1e-5f) * lg[j] + lb[j];
    float hv = gelu_exact(y);
    g_h[v * HID + j] = hv;
    store_ap(v, j, hv);
}

// ---------------- FiLM: gamma/beta ----------------
__global__ void k_film(const float* __restrict__ t, const float* __restrict__ W1,
                       const float* __restrict__ b1, const float* __restrict__ W2,
                       const float* __restrict__ b2) {
    __shared__ float hs[64];
    int tid = threadIdx.x;                     // 256 threads
    float tv = t[0];
    if (tid < 64) hs[tid] = gelu_exact(tv * W1[tid] + b1[tid]);
    __syncthreads();
    float s = b2[tid];
#pragma unroll 8
    for (int k = 0; k < 64; k++) s += hs[k] * W2[k * 256 + tid];
    if (tid < 128) g_gamma[tid] = s; else g_beta[tid - 128] = s;
}

// ---------------- dtype detection (edge_index + mask) ----------------
__global__ void k_pre0(const void* __restrict__ ei, const void* __restrict__ m) {
    int lane = threadIdx.x & 31;
    if (threadIdx.x < 32) {
        const long long* p = (const long long*)ei;
        int bad = 0;
        for (int i = lane; i < 2048; i += 32) {
            long long v = p[i];
            if (v < 0 || v >= NN) bad = 1;
        }
#pragma unroll
        for (int o = 16; o; o >>= 1) bad |= __shfl_xor_sync(0xffffffffu, bad, o);
        if (lane == 0) g_is64 = !bad;
    } else {
        const unsigned* p = (const unsigned*)m;
        int nonf = 0, noni = 0;
        for (int i = lane; i < 1024; i += 32) {
            unsigned v = p[i];
            if (v != 0u && v != 0x3F800000u) nonf = 1;
            if (v != 0u && v != 1u)          noni = 1;
        }
#pragma unroll
        for (int o = 16; o; o >>= 1) {
            nonf |= __shfl_xor_sync(0xffffffffu, nonf, o);
            noni |= __shfl_xor_sync(0xffffffffu, noni, o);
        }
        if (lane == 0) g_mtype = (!nonf) ? 1 : ((!noni) ? 2 : 0);
    }
}

// ---------------- fused: edge conversion + mask normalization + inits ----------------
__global__ void k_pre1(const void* __restrict__ ei, const void* __restrict__ m) {
    int i = blockIdx.x * blockDim.x + threadIdx.x;
    if (i < EE) {
        int s, d;
        if (g_is64) {
            const long long* p = (const long long*)ei;
            s = (int)p[i]; d = (int)p[EE + i];
        } else {
            const int* p = (const int*)ei;
            s = p[i]; d = p[EE + i];
        }
        g_src[i] = s; g_dst[i] = d;
    }
    if (i < NN) {
        g_deg[i] = 0; g_fill[i] = 0;
        float r;
        if (g_mtype == 1)      r = ((const float*)m)[i];
        else if (g_mtype == 2) r = (float)((const int*)m)[i];
        else                   r = (float)((const unsigned char*)m)[i];
        g_mask[i] = (r != 0.0f) ? 0.0f : 1.0f;
    }
    if (i < NN * 4) g_easum[i] = 0.0f;
}

__global__ void k_hist(const float* __restrict__ ea) {
    int e = blockIdx.x * blockDim.x + threadIdx.x;
    if (e >= EE) return;
    int d = g_dst[e];
    if ((unsigned)d >= NN) return;
    atomicAdd(&g_deg[d], 1);
    atomicAdd(&g_easum[d * 4 + 0], ea[e * 4 + 0]);
    atomicAdd(&g_easum[d * 4 + 1], ea[e * 4 + 1]);
    atomicAdd(&g_easum[d * 4 + 2], ea[e * 4 + 2]);
    atomicAdd(&g_easum[d * 4 + 3], ea[e * 4 + 3]);
}

// exclusive scan of (deg+1) over NN entries; 1 block, 1024 threads
__global__ void k_scan() {
    __shared__ int wsum[32];
    int t = threadIdx.x;
    int lane = t & 31, wid = t >> 5;
    const int chunk = (NN + 1023) / 1024;
    int lo = min(t * chunk, NN);
    int hi = min(lo + chunk, NN);
    int s = 0;
    for (int v = lo; v < hi; v++) s += g_deg[v] + 1;
    int incl = s;
#pragma unroll
    for (int o = 1; o < 32; o <<= 1) {
        int n = __shfl_up_sync(0xffffffffu, incl, o);
        if (lane >= o) incl += n;
    }
    if (lane == 31) wsum[wid] = incl;
    __syncthreads();
    if (wid == 0) {
        int v = wsum[lane];
        int wincl = v;
#pragma unroll
        for (int o = 1; o < 32; o <<= 1) {
            int n = __shfl_up_sync(0xffffffffu, wincl, o);
            if (lane >= o) wincl += n;
        }
        wsum[lane] = wincl - v;
    }
    __syncthreads();
    int run = wsum[wid] + (incl - s);
    for (int v = lo; v < hi; v++) { g_rowptr[v] = run; run += g_deg[v] + 1; }
    if (t == 0) g_rowptr[NN] = ETOT;
}

// fused CSR scatter (edges) + self-loop fill (disjoint slots)
__global__ void k_scatter_self(const float* __restrict__ ea) {
    int i = blockIdx.x * blockDim.x + threadIdx.x;
    if (i < EE) {
        int d = g_dst[i];
        if ((unsigned)d < NN) {
            int pos = g_rowptr[d] + atomicAdd(&g_fill[d], 1);
            g_csrc[pos] = g_src[i];
            g_cea4[pos] = make_float4(ea[i * 4 + 0], ea[i * 4 + 1],
                                      ea[i * 4 + 2], ea[i * 4 + 3]);
        }
    } else if (i < EE + NN) {
        int v = i - EE;
        int dg = g_deg[v];
        int pos = g_rowptr[v] + dg;
        g_csrc[pos] = v;
        float inv = 1.0f / fmaxf((float)dg, 1.0f);
        g_cea4[pos] = make_float4(g_easum[v * 4 + 0] * inv, g_easum[v * 4 + 1] * inv,
                                  g_easum[v * 4 + 2] * inv, g_easum[v * 4 + 3] * inv);
    }
}

// ---------------- B conversion: ALL 4 layers -> packed fragments, once --------------------
// pair index p = (((wh*16+ks)*4+sub)*32 + gq*4+tg); u32 view: [p*4+bb]=hi, [p*4+2+bb]=lo
__global__ void k_convB_all(const float* __restrict__ Wl, const float* __restrict__ Wr) {
    int i = blockIdx.x * 256 + threadIdx.x;        // 4 * 32768 total
    int L = i >> 15, r = i & 32767;
    int nt = r >> 13, rr = r & 8191;
    int k = rr >> 6, n = rr & 63;
    const float* W = ((nt < 2) ? Wl : Wr) + L * HID * HID;
    int cbase = (nt & 1) * 64;
    float v = W[k * HID + cbase + n];
    unsigned h = f2tf32(v);
    unsigned l = f2tf32(v - __uint_as_float(h));
    int wh = n >> 5, sub = (n >> 3) & 3, gq = n & 7;
    int ks = k >> 3, tg = k & 3, bb = (k >> 2) & 1;
    int p = (((wh * 16 + ks) * 4 + sub) * 32) + (gq * 4 + tg);
    int base = L * 65536 + nt * 16384 + p * 4;
    g_bfp[base + bb]     = h;
    g_bfp[base + 2 + bb] = l;
}

// ---------------- tensor-core GEMM v3 (3xTF32, zero smem, M_CTA=128) ----------------------
// grid = 391*4: rt = bid>>2 (128-row tile), nt = bid&3 (64-col slice).
// 8 warps: wr = wid>>1 (16-row slice within 64), wh = wid&1 (32-col half).
// Each warp: row blocks (wr*16) and (wr*16+64). Per ks: 4 A LDG.128 + 4 B LDG.128 + 24 mma.
__global__ void __launch_bounds__(256)
k_gemm_tc3(const float* __restrict__ bl, const float* __restrict__ br, int layer) {
    int bid = blockIdx.x;
    int rt = bid >> 2, nt = bid & 3;
    int tid = threadIdx.x;
    int lane = tid & 31, wid = tid >> 5;
    int g = lane >> 2, tg = lane & 3;
    int wr = wid >> 1, wh = wid & 1;
    const float* bsrc = (nt < 2) ? bl : br;
    int cbase = (nt & 1) * 64;
    int row0 = rt * 128;

    const uint4* A4 = (const uint4*)g_ap;          // row stride 64 uint4
    const uint4* B4 = (const uint4*)(g_bfp + layer * 65536 + nt * 16384);

    float c[2][4][4];
#pragma unroll
    for (int rb = 0; rb < 2; rb++)
#pragma unroll
        for (int s0 = 0; s0 < 4; s0++)
#pragma unroll
            for (int s1 = 0; s1 < 4; s1++) c[rb][s0][s1] = 0.0f;

    int ra0 = (row0 + wr * 16 + g) * 64;          // uint4 row base, rb0 row g
#pragma unroll 4
    for (int ks = 0; ks < 16; ks++) {
        int ai = ks * 4 + tg;
        uint4 a0 = A4[ra0 + ai];                  // rb0: row g      [h(c),h(c+4),l(c),l(c+4)]
        uint4 a1 = A4[ra0 + 8 * 64 + ai];         // rb0: row g+8
        uint4 a2 = A4[ra0 + 64 * 64 + ai];        // rb1: row g (+64)
        uint4 a3 = A4[ra0 + 72 * 64 + ai];        // rb1: row g+8 (+64)
#pragma unroll
        for (int sub = 0; sub < 4; sub++) {
            uint4 bf = B4[((wh * 16 + ks) * 4 + sub) * 32 + lane];
            mma8(c[0][sub], a0.x, a1.x, a0.y, a1.y, bf.x, bf.y);
            mma8(c[0][sub], a0.x, a1.x, a0.y, a1.y, bf.z, bf.w);
            mma8(c[0][sub], a0.z, a1.z, a0.w, a1.w, bf.x, bf.y);
            mma8(c[1][sub], a2.x, a3.x, a2.y, a3.y, bf.x, bf.y);
            mma8(c[1][sub], a2.x, a3.x, a2.y, a3.y, bf.z, bf.w);
            mma8(c[1][sub], a2.z, a3.z, a2.w, a3.w, bf.x, bf.y);
        }
    }

    // ---- store with bias ----
#pragma unroll
    for (int rb = 0; rb < 2; rb++) {
        int r0 = row0 + rb * 64 + wr * 16 + g;
        int r1 = r0 + 8;
#pragma unroll
        for (int sub = 0; sub < 4; sub++) {
            int lcol = wh * 32 + sub * 8 + 2 * tg;
            int gcol = nt * 64 + lcol;
            float bv0 = bsrc[cbase + lcol];
            float bv1 = bsrc[cbase + lcol + 1];
            if (r0 < NN) {
                g_xlr[r0 * 256 + gcol]     = c[rb][sub][0] + bv0;
                g_xlr[r0 * 256 + gcol + 1] = c[rb][sub][1] + bv1;
            }
            if (r1 < NN) {
                g_xlr[r1 * 256 + gcol]     = c[rb][sub][2] + bv0;
                g_xlr[r1 * 256 + gcol + 1] = c[rb][sub][3] + bv1;
            }
        }
    }
}

// ---------------- fused node kernel: GATv2 + FiLM + LN + GELU + residual (+ tf32 conv) ----
__global__ void k_node(const float* __restrict__ att, const float* __restrict__ We,
                       const float* __restrict__ bo,  const float* __restrict__ lng,
                       const float* __restrict__ lnb, int doconv) {
    int w = (blockIdx.x * blockDim.x + threadIdx.x) >> 5;
    int lane = threadIdx.x & 31;
    if (w >= NN) return;
    int v = w;
    int c0 = lane * 4;
    float4 attv, we0, we1, we2, we3;
    attv.x = att[c0];     attv.y = att[c0 + 1];     attv.z = att[c0 + 2];     attv.w = att[c0 + 3];
    we0.x = We[c0];       we0.y = We[c0 + 1];       we0.z = We[c0 + 2];       we0.w = We[c0 + 3];
    we1.x = We[128 + c0]; we1.y = We[128 + c0 + 1]; we1.z = We[128 + c0 + 2]; we1.w = We[128 + c0 + 3];
    we2.x = We[256 + c0]; we2.y = We[256 + c0 + 1]; we2.z = We[256 + c0 + 2]; we2.w = We[256 + c0 + 3];
    we3.x = We[384 + c0]; we3.y = We[384 + c0 + 1]; we3.z = We[384 + c0 + 2]; we3.w = We[384 + c0 + 3];
    float4 xr = *(const float4*)(g_xlr + v * 256 + 128 + c0);

    float mh = -1e30f, dh = 0.0f;
    float4 acc = make_float4(0.f, 0.f, 0.f, 0.f);
    int beg = g_rowptr[v], end = g_rowptr[v + 1];
    for (int p = beg; p < end; p++) {
        int s = g_csrc[p];
        float4 ea = g_cea4[p];
        float4 xl = *(const float4*)(g_xlr + s * 256 + c0);
        float4 m;
        m.x = xl.x + xr.x + ea.x * we0.x + ea.y * we1.x + ea.z * we2.x + ea.w * we3.x;
        m.y = xl.y + xr.y + ea.x * we0.y + ea.y * we1.y + ea.z * we2.y + ea.w * we3.y;
        m.z = xl.z + xr.z + ea.x * we0.z + ea.y * we1.z + ea.z * we2.z + ea.w * we3.z;
        m.w = xl.w + xr.w + ea.x * we0.w + ea.y * we1.w + ea.z * we2.w + ea.w * we3.w;
        m.x = m.x > 0.f ? m.x : 0.2f * m.x;
        m.y = m.y > 0.f ? m.y : 0.2f * m.y;
        m.z = m.z > 0.f ? m.z : 0.2f * m.z;
        m.w = m.w > 0.f ? m.w : 0.2f * m.w;
        float ap = m.x * attv.x + m.y * attv.y + m.z * attv.z + m.w * attv.w;
        ap += __shfl_xor_sync(0xffffffffu, ap, 1);
        ap += __shfl_xor_sync(0xffffffffu, ap, 2);
        ap += __shfl_xor_sync(0xffffffffu, ap, 4);
        float mn = fmaxf(mh, ap);
        float sc = __expf(mh - mn);
        float pe = __expf(ap - mn);
        dh = dh * sc + pe;
        acc.x = acc.x * sc + pe * xl.x;
        acc.y = acc.y * sc + pe * xl.y;
        acc.z = acc.z * sc + pe * xl.z;
        acc.w = acc.w * sc + pe * xl.w;
        mh = mn;
    }
    float rd = 1.0f / dh;
    float4 f;
    f.x = g_gamma[c0 + 0] * (acc.x * rd + bo[c0 + 0]) + g_beta[c0 + 0];
    f.y = g_gamma[c0 + 1] * (acc.y * rd + bo[c0 + 1]) + g_beta[c0 + 1];
    f.z = g_gamma[c0 + 2] * (acc.z * rd + bo[c0 + 2]) + g_beta[c0 + 2];
    f.w = g_gamma[c0 + 3] * (acc.w * rd + bo[c0 + 3]) + g_beta[c0 + 3];
    float S  = f.x + f.y + f.z + f.w;
    float S2 = f.x * f.x + f.y * f.y + f.z * f.z + f.w * f.w;
#pragma unroll
    for (int o = 16; o; o >>= 1) {
        S  += __shfl_xor_sync(0xffffffffu, S,  o);
        S2 += __shfl_xor_sync(0xffffffffu, S2, o);
    }
    float mean = S * (1.0f / HID);
    float var  = S2 * (1.0f / HID) - mean * mean;
    float rstd = rsqrtf(var + 1e-5f);
    float4 hold = *(const float4*)(g_h + v * HID + c0);
    float4 hnew;
    hnew.x = gelu_exact((f.x - mean) * rstd * lng[c0 + 0] + lnb[c0 + 0]) + hold.x;
    hnew.y = gelu_exact((f.y - mean) * rstd * lng[c0 + 1] + lnb[c0 + 1]) + hold.y;
    hnew.z = gelu_exact((f.z - mean) * rstd * lng[c0 + 2] + lnb[c0 + 2]) + hold.z;
    hnew.w = gelu_exact((f.w - mean) * rstd * lng[c0 + 3] + lnb[c0 + 3]) + hold.w;
    *(float4*)(g_h + v * HID + c0) = hnew;
    if (doconv) {
        store_ap(v, c0 + 0, hnew.x);
        store_ap(v, c0 + 1, hnew.y);
        store_ap(v, c0 + 2, hnew.z);
        store_ap(v, c0 + 3, hnew.w);
    }
}

// ---------------- decoder ----------------
__global__ void k_dec(const float* __restrict__ x,
                      const float* __restrict__ W1, const float* __restrict__ b1,
                      const float* __restrict__ W2, const float* __restrict__ b2,
                      float* __restrict__ out) {
    __shared__ float W1s[HID * 64];
    __shared__ float b1s[64];
    __shared__ float W2s[128];
    __shared__ float b2s[2];
    __shared__ float hrow[8][HID];
    __shared__ float hmid[8][64];
    int tid = threadIdx.x;                      // 256
    for (int i = tid; i < HID * 64; i += 256) W1s[i] = W1[i];
    if (tid < 64)  b1s[tid] = b1[tid];
    if (tid < 128) W2s[tid] = W2[tid];
    if (tid < 2)   b2s[tid] = b2[tid];
    __syncthreads();
    int wi = tid >> 5, lane = tid & 31;
    int v = blockIdx.x * 8 + wi;
    if (v >= NN) return;
    {
        float4 hv = ((const float4*)(g_h + v * HID))[lane];
        hrow[wi][lane * 4 + 0] = hv.x; hrow[wi][lane * 4 + 1] = hv.y;
        hrow[wi][lane * 4 + 2] = hv.z; hrow[wi][lane * 4 + 3] = hv.w;
    }
    __syncwarp();
#pragma unroll
    for (int cc = lane; cc < 64; cc += 32) {
        float s = b1s[cc];
#pragma unroll 8
        for (int k = 0; k < HID; k++) s += hrow[wi][k] * W1s[k * 64 + cc];
        hmid[wi][cc] = gelu_exact(s);
    }
    __syncwarp();
    float p0 = hmid[wi][lane] * W2s[lane * 2]     + hmid[wi][lane + 32] * W2s[(lane + 32) * 2];
    float p1 = hmid[wi][lane] * W2s[lane * 2 + 1] + hmid[wi][lane + 32] * W2s[(lane + 32) * 2 + 1];
#pragma unroll
    for (int o = 16; o; o >>= 1) {
        p0 += __shfl_xor_sync(0xffffffffu, p0, o);
        p1 += __shfl_xor_sync(0xffffffffu, p1, o);
    }
    if (lane == 0) {
        float d0 = p0 + b2s[0], d1 = p1 + b2s[1];
        d0 = fminf(fmaxf(d0, -50.0f), 50.0f);
        d1 = fminf(fmaxf(d1, -50.0f), 50.0f);
        float mm = g_mask[v];
        d0 *= mm; d1 *= mm;
        out[v * 2 + 0] = x[v * 6 + 0] + d0;
        out[v * 2 + 1] = x[v * 6 + 1] + d1;
        out[NN * 2 + v * 2 + 0] = d0;
        out[NN * 2 + v * 2 + 1] = d1;
    }
}

// ---------------- launch ----------------
// Profiler lands on launch index 3 -> k_gemm_tc3 there.
extern "C" void kernel_launch(void* const* d_in, const int* in_sizes, int n_in,
                              void* d_out, int out_size) {
    const float* x    = (const float*)d_in[0];
    const void*  ei   = d_in[1];
    const float* ea   = (const float*)d_in[2];
    const float* tmp  = (const float*)d_in[3];
    const void*  msk  = d_in[4];
    const float* encW = (const float*)d_in[5];
    const float* encb = (const float*)d_in[6];
    const float* enlg = (const float*)d_in[7];
    const float* enlb = (const float*)d_in[8];
    const float* fW1  = (const float*)d_in[9];
    const float* fb1  = (const float*)d_in[10];
    const float* fW2  = (const float*)d_in[11];
    const float* fb2  = (const float*)d_in[12];
    const float* Wl   = (const float*)d_in[13];
    const float* bl   = (const float*)d_in[14];
    const float* Wr   = (const float*)d_in[15];
    const float* br   = (const float*)d_in[16];
    const float* att  = (const float*)d_in[17];
    const float* We   = (const float*)d_in[18];
    const float* bo   = (const float*)d_in[19];
    const float* lng  = (const float*)d_in[20];
    const float* lnb  = (const float*)d_in[21];
    const float* dW1  = (const float*)d_in[22];
    const float* db1  = (const float*)d_in[23];
    const float* dW2  = (const float*)d_in[24];
    const float* db2  = (const float*)d_in[25];
    float* out = (float*)d_out;

    const int GEMM_GRID = (NPAD / 128) * 4;       // 1564

    k_enc<<<NN, 128>>>(x, encW, encb, enlg, enlb);                    // 0
    k_convB_all<<<512, 256>>>(Wl, Wr);                                // 1
    k_pre0<<<1, 64>>>(ei, msk);                                       // 2
    k_gemm_tc3<<<GEMM_GRID, 256>>>(bl, br, 0);                        // 3 <- profiled
    k_film<<<1, 256>>>(tmp, fW1, fb1, fW2, fb2);                      // 4
    k_pre1<<<(EE + 255) / 256, 256>>>(ei, msk);                       // 5
    k_hist<<<(EE + 255) / 256, 256>>>(ea);                            // 6
    k_scan<<<1, 1024>>>();                                            // 7
    k_scatter_self<<<(EE + NN + 255) / 256, 256>>>(ea);               // 8
    k_node<<<(NN + 7) / 8, 256>>>(att, We, bo, lng, lnb, 1);          // 9

    for (int i = 1; i < 4; i++) {
        k_gemm_tc3<<<GEMM_GRID, 256>>>(bl + i * HID, br + i * HID, i);
        k_node<<<(NN + 7) / 8, 256>>>(att + i * HID, We + i * 4 * HID,
                                      bo + i * HID, lng + i * HID, lnb + i * HID,
                                      (i < 3) ? 1 : 0);
    }
    k_dec<<<(NN + 7) / 8, 256>>>(x, dW1, db1, dW2, db2, out);
}

// round 14
// speedup vs baseline: 1.4266x; 1.4266x over previous
#include <cuda_runtime.h>
#include <cuda_bf16.h>
#include <math.h>

#define NN   50000
#define NPAD 50048                 // 782 * 64
#define EE   400000
#define ETOT (NN + EE)
#define HID  128

// ---------------- scratch (device globals; zero-initialized at load) ----------------
__device__ __align__(16) float    g_h[NN * HID];        // node features
__device__ __align__(16) float    g_xlr[NN * 2 * HID];  // [xl | xr] per row
// packed bf16 A fragments: per row 8 chunks x 4 tg x uint4 {h01,h89,l01,l89} = 256 u16/row
__device__ __align__(16) unsigned short g_ap[NPAD * 256];
// packed bf16 B fragments: 4 layers x 4 nt x 16384 u16
__device__ __align__(16) unsigned short g_bfp[4 * 4 * 16384];
__device__ float  g_easum[NN * 4];
__device__ int    g_deg[NN];
__device__ int    g_fill[NN];
__device__ int    g_rowptr[NN + 1];
__device__ int    g_src[EE];
__device__ int    g_dst[EE];
__device__ int    g_csrc[ETOT];
__device__ float4 g_cea4[ETOT];
__device__ float  g_gamma[HID];
__device__ float  g_beta[HID];
__device__ float  g_mask[NN];
__device__ int    g_is64;
__device__ int    g_mtype;

__device__ __forceinline__ float gelu_exact(float x) {
    return 0.5f * x * (1.0f + erff(x * 0.70710678118654752440f));
}

__device__ __forceinline__ unsigned short bf16bits(float v) {
    __nv_bfloat16 b = __float2bfloat16(v);
    return *reinterpret_cast<unsigned short*>(&b);
}

// write bf16 hi/lo for (row, col) into g_ap (u16-granular; no cross-thread word races)
__device__ __forceinline__ void store_ap(int row, int col, float v) {
    __nv_bfloat16 hb = __float2bfloat16(v);
    float hf = __bfloat162float(hb);
    unsigned short h = *reinterpret_cast<unsigned short*>(&hb);
    unsigned short l = bf16bits(v - hf);
    int ch = col >> 4, kk = col & 15;
    int pos = (kk >= 8) ? 1 : 0;
    int tg = (kk & 7) >> 1;
    int bit = kk & 1;
    int base = row * 256 + ch * 32 + tg * 8 + pos * 2 + bit;
    g_ap[base]     = h;
    g_ap[base + 4] = l;
}

__device__ __forceinline__ void mmabf(float c[4],
                                      unsigned a0, unsigned a1, unsigned a2, unsigned a3,
                                      unsigned b0, unsigned b1) {
    asm volatile("mma.sync.aligned.m16n8k16.row.col.f32.bf16.bf16.f32 "
                 "{%0,%1,%2,%3}, {%4,%5,%6,%7}, {%8,%9}, {%0,%1,%2,%3};"
                 : "+f"(c[0]), "+f"(c[1]), "+f"(c[2]), "+f"(c[3])
                 : "r"(a0), "r"(a1), "r"(a2), "r"(a3), "r"(b0), "r"(b1));
}

// ---------------- encoder: h = gelu(ln(x @ W + b)); writes g_h AND packed bf16 ----------------
__global__ void k_enc(const float* __restrict__ x, const float* __restrict__ W,
                      const float* __restrict__ b, const float* __restrict__ lg,
                      const float* __restrict__ lb) {
    int v = blockIdx.x;
    int j = threadIdx.x;                       // 128 threads; thread j = column j
    __shared__ float xs[8];
    __shared__ float r1[4], r2[4];
    if (j < 6) xs[j] = x[v * 6 + j];
    __syncthreads();
    float s = b[j];
#pragma unroll
    for (int k = 0; k < 6; k++) s += xs[k] * W[k * HID + j];
    float t1 = s, t2 = s * s;
#pragma unroll
    for (int o = 16; o; o >>= 1) {
        t1 += __shfl_xor_sync(0xffffffffu, t1, o);
        t2 += __shfl_xor_sync(0xffffffffu, t2, o);
    }
    int lane = j & 31, w = j >> 5;
    if (lane == 0) { r1[w] = t1; r2[w] = t2; }
    __syncthreads();
    float S1 = r1[0] + r1[1] + r1[2] + r1[3];
    float S2 = r2[0] + r2[1] + r2[2] + r2[3];
    float mean = S1 * (1.0f / HID);
    float var  = S2 * (1.0f / HID) - mean * mean;
    float y = (s - mean) * rsqrtf(var + 1e-5f) * lg[j] + lb[j];
    float hv = gelu_exact(y);
    g_h[v * HID + j] = hv;
    store_ap(v, j, hv);
}

// ---------------- FiLM: gamma/beta ----------------
__global__ void k_film(const float* __restrict__ t, const float* __restrict__ W1,
                       const float* __restrict__ b1, const float* __restrict__ W2,
                       const float* __restrict__ b2) {
    __shared__ float hs[64];
    int tid = threadIdx.x;                     // 256 threads
    float tv = t[0];
    if (tid < 64) hs[tid] = gelu_exact(tv * W1[tid] + b1[tid]);
    __syncthreads();
    float s = b2[tid];
#pragma unroll 8
    for (int k = 0; k < 64; k++) s += hs[k] * W2[k * 256 + tid];
    if (tid < 128) g_gamma[tid] = s; else g_beta[tid - 128] = s;
}

// ---------------- dtype detection (edge_index + mask) ----------------
__global__ void k_pre0(const void* __restrict__ ei, const void* __restrict__ m) {
    int lane = threadIdx.x & 31;
    if (threadIdx.x < 32) {
        const long long* p = (const long long*)ei;
        int bad = 0;
        for (int i = lane; i < 2048; i += 32) {
            long long v = p[i];
            if (v < 0 || v >= NN) bad = 1;
        }
#pragma unroll
        for (int o = 16; o; o >>= 1) bad |= __shfl_xor_sync(0xffffffffu, bad, o);
        if (lane == 0) g_is64 = !bad;
    } else {
        const unsigned* p = (const unsigned*)m;
        int nonf = 0, noni = 0;
        for (int i = lane; i < 1024; i += 32) {
            unsigned v = p[i];
            if (v != 0u && v != 0x3F800000u) nonf = 1;
            if (v != 0u && v != 1u)          noni = 1;
        }
#pragma unroll
        for (int o = 16; o; o >>= 1) {
            nonf |= __shfl_xor_sync(0xffffffffu, nonf, o);
            noni |= __shfl_xor_sync(0xffffffffu, noni, o);
        }
        if (lane == 0) g_mtype = (!nonf) ? 1 : ((!noni) ? 2 : 0);
    }
}

// ---------------- fused: edge conversion + mask normalization + inits ----------------
__global__ void k_pre1(const void* __restrict__ ei, const void* __restrict__ m) {
    int i = blockIdx.x * blockDim.x + threadIdx.x;
    if (i < EE) {
        int s, d;
        if (g_is64) {
            const long long* p = (const long long*)ei;
            s = (int)p[i]; d = (int)p[EE + i];
        } else {
            const int* p = (const int*)ei;
            s = p[i]; d = p[EE + i];
        }
        g_src[i] = s; g_dst[i] = d;
    }
    if (i < NN) {
        g_deg[i] = 0; g_fill[i] = 0;
        float r;
        if (g_mtype == 1)      r = ((const float*)m)[i];
        else if (g_mtype == 2) r = (float)((const int*)m)[i];
        else                   r = (float)((const unsigned char*)m)[i];
        g_mask[i] = (r != 0.0f) ? 0.0f : 1.0f;
    }
    if (i < NN * 4) g_easum[i] = 0.0f;
}

__global__ void k_hist(const float* __restrict__ ea) {
    int e = blockIdx.x * blockDim.x + threadIdx.x;
    if (e >= EE) return;
    int d = g_dst[e];
    if ((unsigned)d >= NN) return;
    atomicAdd(&g_deg[d], 1);
    atomicAdd(&g_easum[d * 4 + 0], ea[e * 4 + 0]);
    atomicAdd(&g_easum[d * 4 + 1], ea[e * 4 + 1]);
    atomicAdd(&g_easum[d * 4 + 2], ea[e * 4 + 2]);
    atomicAdd(&g_easum[d * 4 + 3], ea[e * 4 + 3]);
}

// exclusive scan of (deg+1) over NN entries; 1 block, 1024 threads
__global__ void k_scan() {
    __shared__ int wsum[32];
    int t = threadIdx.x;
    int lane = t & 31, wid = t >> 5;
    const int chunk = (NN + 1023) / 1024;
    int lo = min(t * chunk, NN);
    int hi = min(lo + chunk, NN);
    int s = 0;
    for (int v = lo; v < hi; v++) s += g_deg[v] + 1;
    int incl = s;
#pragma unroll
    for (int o = 1; o < 32; o <<= 1) {
        int n = __shfl_up_sync(0xffffffffu, incl, o);
        if (lane >= o) incl += n;
    }
    if (lane == 31) wsum[wid] = incl;
    __syncthreads();
    if (wid == 0) {
        int v = wsum[lane];
        int wincl = v;
#pragma unroll
        for (int o = 1; o < 32; o <<= 1) {
            int n = __shfl_up_sync(0xffffffffu, wincl, o);
            if (lane >= o) wincl += n;
        }
        wsum[lane] = wincl - v;
    }
    __syncthreads();
    int run = wsum[wid] + (incl - s);
    for (int v = lo; v < hi; v++) { g_rowptr[v] = run; run += g_deg[v] + 1; }
    if (t == 0) g_rowptr[NN] = ETOT;
}

// fused CSR scatter (edges) + self-loop fill (disjoint slots)
__global__ void k_scatter_self(const float* __restrict__ ea) {
    int i = blockIdx.x * blockDim.x + threadIdx.x;
    if (i < EE) {
        int d = g_dst[i];
        if ((unsigned)d < NN) {
            int pos = g_rowptr[d] + atomicAdd(&g_fill[d], 1);
            g_csrc[pos] = g_src[i];
            g_cea4[pos] = make_float4(ea[i * 4 + 0], ea[i * 4 + 1],
                                      ea[i * 4 + 2], ea[i * 4 + 3]);
        }
    } else if (i < EE + NN) {
        int v = i - EE;
        int dg = g_deg[v];
        int pos = g_rowptr[v] + dg;
        g_csrc[pos] = v;
        float inv = 1.0f / fmaxf((float)dg, 1.0f);
        g_cea4[pos] = make_float4(g_easum[v * 4 + 0] * inv, g_easum[v * 4 + 1] * inv,
                                  g_easum[v * 4 + 2] * inv, g_easum[v * 4 + 3] * inv);
    }
}

// ---------------- B conversion: ALL 4 layers -> packed bf16 fragments, once ---------------
__global__ void k_convB_all(const float* __restrict__ Wl, const float* __restrict__ Wr) {
    int i = blockIdx.x * 256 + threadIdx.x;        // 4L * 4nt * 8192 = 131072 total
    int L = i >> 15, r = i & 32767;
    int nt = r >> 13, rr = r & 8191;
    int k = rr >> 6, n = rr & 63;
    const float* W = ((nt < 2) ? Wl : Wr) + L * HID * HID;
    int cbase = (nt & 1) * 64;
    float v = W[k * HID + cbase + n];
    __nv_bfloat16 hb = __float2bfloat16(v);
    float hf = __bfloat162float(hb);
    unsigned short h = *reinterpret_cast<unsigned short*>(&hb);
    unsigned short l = bf16bits(v - hf);
    int wh = n >> 5, sub = (n >> 3) & 3, g = n & 7;
    int ch = k >> 4, kk = k & 15;
    int pos = (kk >= 8) ? 1 : 0;
    int tg = (kk & 7) >> 1;
    int bit = kk & 1;
    int lane = g * 4 + tg;
    int base = (L * 4 + nt) * 16384
             + ((((wh * 8 + ch) * 4 + sub) * 32) + lane) * 8 + pos * 2 + bit;
    g_bfp[base]     = h;
    g_bfp[base + 4] = l;
}

// ---------------- tensor-core GEMM v4 (bf16x2, m16n8k16, zero smem, M_CTA=64) -------------
// grid = 782*4: rt = bid>>2 (64-row tile), nt = bid&3 (64-col slice).
// 8 warps: wr = wid>>1 (16-row slice), wh = wid&1 (32-col half).
// Per chunk (k16, 8 chunks): 2 A LDG.128 + 4 B LDG.128 + 12 mma.
__global__ void __launch_bounds__(256)
k_gemm_tc4(const float* __restrict__ bl, const float* __restrict__ br, int layer) {
    int bid = blockIdx.x;
    int rt = bid >> 2, nt = bid & 3;
    int tid = threadIdx.x;
    int lane = tid & 31, wid = tid >> 5;
    int g = lane >> 2, tg = lane & 3;
    int wr = wid >> 1, wh = wid & 1;
    const float* bsrc = (nt < 2) ? bl : br;
    int cbase = (nt & 1) * 64;
    int row0 = rt * 64;

    const uint4* A4 = (const uint4*)g_ap;                       // row stride 32 uint4
    const uint4* B4 = (const uint4*)(g_bfp + (layer * 4 + nt) * 16384);

    float c[4][4];
#pragma unroll
    for (int s0 = 0; s0 < 4; s0++)
#pragma unroll
        for (int s1 = 0; s1 < 4; s1++) c[s0][s1] = 0.0f;

    int ra  = (row0 + wr * 16 + g) * 32;                        // uint4 row base, row g
    int ra8 = ra + 8 * 32;                                      // row g+8
#pragma unroll
    for (int ch = 0; ch < 8; ch++) {
        int ai = ch * 4 + tg;
        uint4 ag  = A4[ra + ai];     // {h(2tg,2tg+1), h(2tg+8,2tg+9), l(..), l(..)} row g
        uint4 ag8 = A4[ra8 + ai];    // row g+8
#pragma unroll
        for (int sub = 0; sub < 4; sub++) {
            uint4 bf = B4[(((wh * 8 + ch) * 4 + sub) * 32) + lane];
            mmabf(c[sub], ag.x, ag8.x, ag.y, ag8.y, bf.x, bf.y);   // hi*hi
            mmabf(c[sub], ag.x, ag8.x, ag.y, ag8.y, bf.z, bf.w);   // hi*lo
            mmabf(c[sub], ag.z, ag8.z, ag.w, ag8.w, bf.x, bf.y);   // lo*hi
        }
    }

    // ---- store with bias ----
    int r0 = row0 + wr * 16 + g;
    int r1 = r0 + 8;
#pragma unroll
    for (int sub = 0; sub < 4; sub++) {
        int lcol = wh * 32 + sub * 8 + 2 * tg;
        int gcol = nt * 64 + lcol;
        float bv0 = bsrc[cbase + lcol];
        float bv1 = bsrc[cbase + lcol + 1];
        if (r0 < NN) {
            g_xlr[r0 * 256 + gcol]     = c[sub][0] + bv0;
            g_xlr[r0 * 256 + gcol + 1] = c[sub][1] + bv1;
        }
        if (r1 < NN) {
            g_xlr[r1 * 256 + gcol]     = c[sub][2] + bv0;
            g_xlr[r1 * 256 + gcol + 1] = c[sub][3] + bv1;
        }
    }
}

// ---------------- fused node kernel: GATv2 + FiLM + LN + GELU + residual (+ bf16 conv) ----
__global__ void k_node(const float* __restrict__ att, const float* __restrict__ We,
                       const float* __restrict__ bo,  const float* __restrict__ lng,
                       const float* __restrict__ lnb, int doconv) {
    int w = (blockIdx.x * blockDim.x + threadIdx.x) >> 5;
    int lane = threadIdx.x & 31;
    if (w >= NN) return;
    int v = w;
    int c0 = lane * 4;
    float4 attv, we0, we1, we2, we3;
    attv.x = att[c0];     attv.y = att[c0 + 1];     attv.z = att[c0 + 2];     attv.w = att[c0 + 3];
    we0.x = We[c0];       we0.y = We[c0 + 1];       we0.z = We[c0 + 2];       we0.w = We[c0 + 3];
    we1.x = We[128 + c0]; we1.y = We[128 + c0 + 1]; we1.z = We[128 + c0 + 2]; we1.w = We[128 + c0 + 3];
    we2.x = We[256 + c0]; we2.y = We[256 + c0 + 1]; we2.z = We[256 + c0 + 2]; we2.w = We[256 + c0 + 3];
    we3.x = We[384 + c0]; we3.y = We[384 + c0 + 1]; we3.z = We[384 + c0 + 2]; we3.w = We[384 + c0 + 3];
    float4 xr = *(const float4*)(g_xlr + v * 256 + 128 + c0);

    float mh = -1e30f, dh = 0.0f;
    float4 acc = make_float4(0.f, 0.f, 0.f, 0.f);
    int beg = g_rowptr[v], end = g_rowptr[v + 1];
    for (int p = beg; p < end; p++) {
        int s = g_csrc[p];
        float4 ea = g_cea4[p];
        float4 xl = *(const float4*)(g_xlr + s * 256 + c0);
        float4 m;
        m.x = xl.x + xr.x + ea.x * we0.x + ea.y * we1.x + ea.z * we2.x + ea.w * we3.x;
        m.y = xl.y + xr.y + ea.x * we0.y + ea.y * we1.y + ea.z * we2.y + ea.w * we3.y;
        m.z = xl.z + xr.z + ea.x * we0.z + ea.y * we1.z + ea.z * we2.z + ea.w * we3.z;
        m.w = xl.w + xr.w + ea.x * we0.w + ea.y * we1.w + ea.z * we2.w + ea.w * we3.w;
        m.x = m.x > 0.f ? m.x : 0.2f * m.x;
        m.y = m.y > 0.f ? m.y : 0.2f * m.y;
        m.z = m.z > 0.f ? m.z : 0.2f * m.z;
        m.w = m.w > 0.f ? m.w : 0.2f * m.w;
        float ap = m.x * attv.x + m.y * attv.y + m.z * attv.z + m.w * attv.w;
        ap += __shfl_xor_sync(0xffffffffu, ap, 1);
        ap += __shfl_xor_sync(0xffffffffu, ap, 2);
        ap += __shfl_xor_sync(0xffffffffu, ap, 4);
        float mn = fmaxf(mh, ap);
        float sc = __expf(mh - mn);
        float pe = __expf(ap - mn);
        dh = dh * sc + pe;
        acc.x = acc.x * sc + pe * xl.x;
        acc.y = acc.y * sc + pe * xl.y;
        acc.z = acc.z * sc + pe * xl.z;
        acc.w = acc.w * sc + pe * xl.w;
        mh = mn;
    }
    float rd = 1.0f / dh;
    float4 f;
    f.x = g_gamma[c0 + 0] * (acc.x * rd + bo[c0 + 0]) + g_beta[c0 + 0];
    f.y = g_gamma[c0 + 1] * (acc.y * rd + bo[c0 + 1]) + g_beta[c0 + 1];
    f.z = g_gamma[c0 + 2] * (acc.z * rd + bo[c0 + 2]) + g_beta[c0 + 2];
    f.w = g_gamma[c0 + 3] * (acc.w * rd + bo[c0 + 3]) + g_beta[c0 + 3];
    float S  = f.x + f.y + f.z + f.w;
    float S2 = f.x * f.x + f.y * f.y + f.z * f.z + f.w * f.w;
#pragma unroll
    for (int o = 16; o; o >>= 1) {
        S  += __shfl_xor_sync(0xffffffffu, S,  o);
        S2 += __shfl_xor_sync(0xffffffffu, S2, o);
    }
    float mean = S * (1.0f / HID);
    float var  = S2 * (1.0f / HID) - mean * mean;
    float rstd = rsqrtf(var + 1e-5f);
    float4 hold = *(const float4*)(g_h + v * HID + c0);
    float4 hnew;
    hnew.x = gelu_exact((f.x - mean) * rstd * lng[c0 + 0] + lnb[c0 + 0]) + hold.x;
    hnew.y = gelu_exact((f.y - mean) * rstd * lng[c0 + 1] + lnb[c0 + 1]) + hold.y;
    hnew.z = gelu_exact((f.z - mean) * rstd * lng[c0 + 2] + lnb[c0 + 2]) + hold.z;
    hnew.w = gelu_exact((f.w - mean) * rstd * lng[c0 + 3] + lnb[c0 + 3]) + hold.w;
    *(float4*)(g_h + v * HID + c0) = hnew;
    if (doconv) {
        store_ap(v, c0 + 0, hnew.x);
        store_ap(v, c0 + 1, hnew.y);
        store_ap(v, c0 + 2, hnew.z);
        store_ap(v, c0 + 3, hnew.w);
    }
}

// ---------------- decoder ----------------
__global__ void k_dec(const float* __restrict__ x,
                      const float* __restrict__ W1, const float* __restrict__ b1,
                      const float* __restrict__ W2, const float* __restrict__ b2,
                      float* __restrict__ out) {
    __shared__ float W1s[HID * 64];
    __shared__ float b1s[64];
    __shared__ float W2s[128];
    __shared__ float b2s[2];
    __shared__ float hrow[8][HID];
    __shared__ float hmid[8][64];
    int tid = threadIdx.x;                      // 256
    for (int i = tid; i < HID * 64; i += 256) W1s[i] = W1[i];
    if (tid < 64)  b1s[tid] = b1[tid];
    if (tid < 128) W2s[tid] = W2[tid];
    if (tid < 2)   b2s[tid] = b2[tid];
    __syncthreads();
    int wi = tid >> 5, lane = tid & 31;
    int v = blockIdx.x * 8 + wi;
    if (v >= NN) return;
    {
        float4 hv = ((const float4*)(g_h + v * HID))[lane];
        hrow[wi][lane * 4 + 0] = hv.x; hrow[wi][lane * 4 + 1] = hv.y;
        hrow[wi][lane * 4 + 2] = hv.z; hrow[wi][lane * 4 + 3] = hv.w;
    }
    __syncwarp();
#pragma unroll
    for (int cc = lane; cc < 64; cc += 32) {
        float s = b1s[cc];
#pragma unroll 8
        for (int k = 0; k < HID; k++) s += hrow[wi][k] * W1s[k * 64 + cc];
        hmid[wi][cc] = gelu_exact(s);
    }
    __syncwarp();
    float p0 = hmid[wi][lane] * W2s[lane * 2]     + hmid[wi][lane + 32] * W2s[(lane + 32) * 2];
    float p1 = hmid[wi][lane] * W2s[lane * 2 + 1] + hmid[wi][lane + 32] * W2s[(lane + 32) * 2 + 1];
#pragma unroll
    for (int o = 16; o; o >>= 1) {
        p0 += __shfl_xor_sync(0xffffffffu, p0, o);
        p1 += __shfl_xor_sync(0xffffffffu, p1, o);
    }
    if (lane == 0) {
        float d0 = p0 + b2s[0], d1 = p1 + b2s[1];
        d0 = fminf(fmaxf(d0, -50.0f), 50.0f);
        d1 = fminf(fmaxf(d1, -50.0f), 50.0f);
        float mm = g_mask[v];
        d0 *= mm; d1 *= mm;
        out[v * 2 + 0] = x[v * 6 + 0] + d0;
        out[v * 2 + 1] = x[v * 6 + 1] + d1;
        out[NN * 2 + v * 2 + 0] = d0;
        out[NN * 2 + v * 2 + 1] = d1;
    }
}

// ---------------- launch ----------------
// Profiler lands on launch index 3 -> k_gemm_tc4 there.
extern "C" void kernel_launch(void* const* d_in, const int* in_sizes, int n_in,
                              void* d_out, int out_size) {
    const float* x    = (const float*)d_in[0];
    const void*  ei   = d_in[1];
    const float* ea   = (const float*)d_in[2];
    const float* tmp  = (const float*)d_in[3];
    const void*  msk  = d_in[4];
    const float* encW = (const float*)d_in[5];
    const float* encb = (const float*)d_in[6];
    const float* enlg = (const float*)d_in[7];
    const float* enlb = (const float*)d_in[8];
    const float* fW1  = (const float*)d_in[9];
    const float* fb1  = (const float*)d_in[10];
    const float* fW2  = (const float*)d_in[11];
    const float* fb2  = (const float*)d_in[12];
    const float* Wl   = (const float*)d_in[13];
    const float* bl   = (const float*)d_in[14];
    const float* Wr   = (const float*)d_in[15];
    const float* br   = (const float*)d_in[16];
    const float* att  = (const float*)d_in[17];
    const float* We   = (const float*)d_in[18];
    const float* bo   = (const float*)d_in[19];
    const float* lng  = (const float*)d_in[20];
    const float* lnb  = (const float*)d_in[21];
    const float* dW1  = (const float*)d_in[22];
    const float* db1  = (const float*)d_in[23];
    const float* dW2  = (const float*)d_in[24];
    const float* db2  = (const float*)d_in[25];
    float* out = (float*)d_out;

    const int GEMM_GRID = (NPAD / 64) * 4;        // 3128

    k_enc<<<NN, 128>>>(x, encW, encb, enlg, enlb);                    // 0
    k_convB_all<<<512, 256>>>(Wl, Wr);                                // 1
    k_pre0<<<1, 64>>>(ei, msk);                                       // 2
    k_gemm_tc4<<<GEMM_GRID, 256>>>(bl, br, 0);                        // 3 <- profiled
    k_film<<<1, 256>>>(tmp, fW1, fb1, fW2, fb2);                      // 4
    k_pre1<<<(EE + 255) / 256, 256>>>(ei, msk);                       // 5
    k_hist<<<(EE + 255) / 256, 256>>>(ea);                            // 6
    k_scan<<<1, 1024>>>();                                            // 7
    k_scatter_self<<<(EE + NN + 255) / 256, 256>>>(ea);               // 8
    k_node<<<(NN + 7) / 8, 256>>>(att, We, bo, lng, lnb, 1);          // 9

    for (int i = 1; i < 4; i++) {
        k_gemm_tc4<<<GEMM_GRID, 256>>>(bl + i * HID, br + i * HID, i);
        k_node<<<(NN + 7) / 8, 256>>>(att + i * HID, We + i * 4 * HID,
                                      bo + i * HID, lng + i * HID, lnb + i * HID,
                                      (i < 3) ? 1 : 0);
    }
    k_dec<<<(NN + 7) / 8, 256>>>(x, dW1, db1, dW2, db2, out);
}

// round 15
// speedup vs baseline: 1.4630x; 1.0255x over previous
#include <cuda_runtime.h>
#include <cuda_bf16.h>
#include <math.h>

#define NN   50000
#define NPAD 50048                 // 391 * 128
#define EE   400000
#define ETOT (NN + EE)
#define HID  128

// ---------------- scratch (device globals; zero-initialized at load) ----------------
__device__ __align__(16) float    g_h[NN * HID];        // node features
__device__ __align__(16) float    g_xlr[NN * 2 * HID];  // [xl | xr] per row
// packed bf16 A fragments: per row 8 chunks x 4 tg x uint4 {h01,h89,l01,l89} = 256 u16/row
__device__ __align__(16) unsigned short g_ap[NPAD * 256];
// packed bf16 B fragments: 4 layers x 4 nt x 16384 u16
__device__ __align__(16) unsigned short g_bfp[4 * 4 * 16384];
__device__ float  g_easum[NN * 4];
__device__ int    g_deg[NN];
__device__ int    g_fill[NN];
__device__ int    g_rowptr[NN + 1];
__device__ int    g_src[EE];
__device__ int    g_dst[EE];
__device__ int    g_csrc[ETOT];
__device__ float4 g_cea4[ETOT];
__device__ float  g_gamma[HID];
__device__ float  g_beta[HID];
__device__ float  g_mask[NN];
__device__ int    g_is64;
__device__ int    g_mtype;

__device__ __forceinline__ float gelu_exact(float x) {
    return 0.5f * x * (1.0f + erff(x * 0.70710678118654752440f));
}

__device__ __forceinline__ unsigned short bf16bits(float v) {
    __nv_bfloat16 b = __float2bfloat16(v);
    return *reinterpret_cast<unsigned short*>(&b);
}

// write bf16 hi/lo for (row, col) into g_ap (u16-granular; no cross-thread word races)
__device__ __forceinline__ void store_ap(int row, int col, float v) {
    __nv_bfloat16 hb = __float2bfloat16(v);
    float hf = __bfloat162float(hb);
    unsigned short h = *reinterpret_cast<unsigned short*>(&hb);
    unsigned short l = bf16bits(v - hf);
    int ch = col >> 4, kk = col & 15;
    int pos = (kk >= 8) ? 1 : 0;
    int tg = (kk & 7) >> 1;
    int bit = kk & 1;
    int base = row * 256 + ch * 32 + tg * 8 + pos * 2 + bit;
    g_ap[base]     = h;
    g_ap[base + 4] = l;
}

__device__ __forceinline__ void mmabf(float c[4],
                                      unsigned a0, unsigned a1, unsigned a2, unsigned a3,
                                      unsigned b0, unsigned b1) {
    asm volatile("mma.sync.aligned.m16n8k16.row.col.f32.bf16.bf16.f32 "
                 "{%0,%1,%2,%3}, {%4,%5,%6,%7}, {%8,%9}, {%0,%1,%2,%3};"
                 : "+f"(c[0]), "+f"(c[1]), "+f"(c[2]), "+f"(c[3])
                 : "r"(a0), "r"(a1), "r"(a2), "r"(a3), "r"(b0), "r"(b1));
}

// ---------------- encoder: h = gelu(ln(x @ W + b)); writes g_h AND packed bf16 ----------------
__global__ void k_enc(const float* __restrict__ x, const float* __restrict__ W,
                      const float* __restrict__ b, const float* __restrict__ lg,
                      const float* __restrict__ lb) {
    int v = blockIdx.x;
    int j = threadIdx.x;                       // 128 threads; thread j = column j
    __shared__ float xs[8];
    __shared__ float r1[4], r2[4];
    if (j < 6) xs[j] = x[v * 6 + j];
    __syncthreads();
    float s = b[j];
#pragma unroll
    for (int k = 0; k < 6; k++) s += xs[k] * W[k * HID + j];
    float t1 = s, t2 = s * s;
#pragma unroll
    for (int o = 16; o; o >>= 1) {
        t1 += __shfl_xor_sync(0xffffffffu, t1, o);
        t2 += __shfl_xor_sync(0xffffffffu, t2, o);
    }
    int lane = j & 31, w = j >> 5;
    if (lane == 0) { r1[w] = t1; r2[w] = t2; }
    __syncthreads();
    float S1 = r1[0] + r1[1] + r1[2] + r1[3];
    float S2 = r2[0] + r2[1] + r2[2] + r2[3];
    float mean = S1 * (1.0f / HID);
    float var  = S2 * (1.0f / HID) - mean * mean;
    float y = (s - mean) * rsqrtf(var + 1e-5f) * lg[j] + lb[j];
    float hv = gelu_exact(y);
    g_h[v * HID + j] = hv;
    store_ap(v, j, hv);
}

// ---------------- FiLM: gamma/beta ----------------
__global__ void k_film(const float* __restrict__ t, const float* __restrict__ W1,
                       const float* __restrict__ b1, const float* __restrict__ W2,
                       const float* __restrict__ b2) {
    __shared__ float hs[64];
    int tid = threadIdx.x;                     // 256 threads
    float tv = t[0];
    if (tid < 64) hs[tid] = gelu_exact(tv * W1[tid] + b1[tid]);
    __syncthreads();
    float s = b2[tid];
#pragma unroll 8
    for (int k = 0; k < 64; k++) s += hs[k] * W2[k * 256 + tid];
    if (tid < 128) g_gamma[tid] = s; else g_beta[tid - 128] = s;
}

// ---------------- dtype detection (edge_index + mask) ----------------
__global__ void k_pre0(const void* __restrict__ ei, const void* __restrict__ m) {
    int lane = threadIdx.x & 31;
    if (threadIdx.x < 32) {
        const long long* p = (const long long*)ei;
        int bad = 0;
        for (int i = lane; i < 2048; i += 32) {
            long long v = p[i];
            if (v < 0 || v >= NN) bad = 1;
        }
#pragma unroll
        for (int o = 16; o; o >>= 1) bad |= __shfl_xor_sync(0xffffffffu, bad, o);
        if (lane == 0) g_is64 = !bad;
    } else {
        const unsigned* p = (const unsigned*)m;
        int nonf = 0, noni = 0;
        for (int i = lane; i < 1024; i += 32) {
            unsigned v = p[i];
            if (v != 0u && v != 0x3F800000u) nonf = 1;
            if (v != 0u && v != 1u)          noni = 1;
        }
#pragma unroll
        for (int o = 16; o; o >>= 1) {
            nonf |= __shfl_xor_sync(0xffffffffu, nonf, o);
            noni |= __shfl_xor_sync(0xffffffffu, noni, o);
        }
        if (lane == 0) g_mtype = (!nonf) ? 1 : ((!noni) ? 2 : 0);
    }
}

// ---------------- fused: edge conversion + mask normalization + inits ----------------
__global__ void k_pre1(const void* __restrict__ ei, const void* __restrict__ m) {
    int i = blockIdx.x * blockDim.x + threadIdx.x;
    if (i < EE) {
        int s, d;
        if (g_is64) {
            const long long* p = (const long long*)ei;
            s = (int)p[i]; d = (int)p[EE + i];
        } else {
            const int* p = (const int*)ei;
            s = p[i]; d = p[EE + i];
        }
        g_src[i] = s; g_dst[i] = d;
    }
    if (i < NN) {
        g_deg[i] = 0; g_fill[i] = 0;
        float r;
        if (g_mtype == 1)      r = ((const float*)m)[i];
        else if (g_mtype == 2) r = (float)((const int*)m)[i];
        else                   r = (float)((const unsigned char*)m)[i];
        g_mask[i] = (r != 0.0f) ? 0.0f : 1.0f;
    }
    if (i < NN * 4) g_easum[i] = 0.0f;
}

__global__ void k_hist(const float* __restrict__ ea) {
    int e = blockIdx.x * blockDim.x + threadIdx.x;
    if (e >= EE) return;
    int d = g_dst[e];
    if ((unsigned)d >= NN) return;
    atomicAdd(&g_deg[d], 1);
    atomicAdd(&g_easum[d * 4 + 0], ea[e * 4 + 0]);
    atomicAdd(&g_easum[d * 4 + 1], ea[e * 4 + 1]);
    atomicAdd(&g_easum[d * 4 + 2], ea[e * 4 + 2]);
    atomicAdd(&g_easum[d * 4 + 3], ea[e * 4 + 3]);
}

// exclusive scan of (deg+1) over NN entries; 1 block, 1024 threads
__global__ void k_scan() {
    __shared__ int wsum[32];
    int t = threadIdx.x;
    int lane = t & 31, wid = t >> 5;
    const int chunk = (NN + 1023) / 1024;
    int lo = min(t * chunk, NN);
    int hi = min(lo + chunk, NN);
    int s = 0;
    for (int v = lo; v < hi; v++) s += g_deg[v] + 1;
    int incl = s;
#pragma unroll
    for (int o = 1; o < 32; o <<= 1) {
        int n = __shfl_up_sync(0xffffffffu, incl, o);
        if (lane >= o) incl += n;
    }
    if (lane == 31) wsum[wid] = incl;
    __syncthreads();
    if (wid == 0) {
        int v = wsum[lane];
        int wincl = v;
#pragma unroll
        for (int o = 1; o < 32; o <<= 1) {
            int n = __shfl_up_sync(0xffffffffu, wincl, o);
            if (lane >= o) wincl += n;
        }
        wsum[lane] = wincl - v;
    }
    __syncthreads();
    int run = wsum[wid] + (incl - s);
    for (int v = lo; v < hi; v++) { g_rowptr[v] = run; run += g_deg[v] + 1; }
    if (t == 0) g_rowptr[NN] = ETOT;
}

// fused CSR scatter (edges) + self-loop fill (disjoint slots)
__global__ void k_scatter_self(const float* __restrict__ ea) {
    int i = blockIdx.x * blockDim.x + threadIdx.x;
    if (i < EE) {
        int d = g_dst[i];
        if ((unsigned)d < NN) {
            int pos = g_rowptr[d] + atomicAdd(&g_fill[d], 1);
            g_csrc[pos] = g_src[i];
            g_cea4[pos] = make_float4(ea[i * 4 + 0], ea[i * 4 + 1],
                                      ea[i * 4 + 2], ea[i * 4 + 3]);
        }
    } else if (i < EE + NN) {
        int v = i - EE;
        int dg = g_deg[v];
        int pos = g_rowptr[v] + dg;
        g_csrc[pos] = v;
        float inv = 1.0f / fmaxf((float)dg, 1.0f);
        g_cea4[pos] = make_float4(g_easum[v * 4 + 0] * inv, g_easum[v * 4 + 1] * inv,
                                  g_easum[v * 4 + 2] * inv, g_easum[v * 4 + 3] * inv);
    }
}

// ---------------- B conversion: ALL 4 layers -> packed bf16 fragments, once ---------------
__global__ void k_convB_all(const float* __restrict__ Wl, const float* __restrict__ Wr) {
    int i = blockIdx.x * 256 + threadIdx.x;        // 4L * 4nt * 8192 = 131072 total
    int L = i >> 15, r = i & 32767;
    int nt = r >> 13, rr = r & 8191;
    int k = rr >> 6, n = rr & 63;
    const float* W = ((nt < 2) ? Wl : Wr) + L * HID * HID;
    int cbase = (nt & 1) * 64;
    float v = W[k * HID + cbase + n];
    __nv_bfloat16 hb = __float2bfloat16(v);
    float hf = __bfloat162float(hb);
    unsigned short h = *reinterpret_cast<unsigned short*>(&hb);
    unsigned short l = bf16bits(v - hf);
    int wh = n >> 5, sub = (n >> 3) & 3, g = n & 7;
    int ch = k >> 4, kk = k & 15;
    int pos = (kk >= 8) ? 1 : 0;
    int tg = (kk & 7) >> 1;
    int bit = kk & 1;
    int lane = g * 4 + tg;
    int base = (L * 4 + nt) * 16384
             + ((((wh * 8 + ch) * 4 + sub) * 32) + lane) * 8 + pos * 2 + bit;
    g_bfp[base]     = h;
    g_bfp[base + 4] = l;
}

// ---------------- tensor-core GEMM v5 (bf16x2, m16n8k16, zero smem, M_CTA=128) ------------
// grid = 391*4: rt = bid>>2 (128-row tile), nt = bid&3 (64-col slice).
// 8 warps: wr = wid>>1 (16-row slice within 64), wh = wid&1 (32-col half).
// Each warp handles row blocks (wr*16) and (wr*16+64); B fragments amortized over both.
__global__ void __launch_bounds__(256)
k_gemm_tc5(const float* __restrict__ bl, const float* __restrict__ br, int layer) {
    int bid = blockIdx.x;
    int rt = bid >> 2, nt = bid & 3;
    int tid = threadIdx.x;
    int lane = tid & 31, wid = tid >> 5;
    int g = lane >> 2, tg = lane & 3;
    int wr = wid >> 1, wh = wid & 1;
    const float* bsrc = (nt < 2) ? bl : br;
    int cbase = (nt & 1) * 64;
    int row0 = rt * 128;

    const uint4* A4 = (const uint4*)g_ap;                       // row stride 32 uint4
    const uint4* B4 = (const uint4*)(g_bfp + (layer * 4 + nt) * 16384);

    float c[2][4][4];
#pragma unroll
    for (int rb = 0; rb < 2; rb++)
#pragma unroll
        for (int s0 = 0; s0 < 4; s0++)
#pragma unroll
            for (int s1 = 0; s1 < 4; s1++) c[rb][s0][s1] = 0.0f;

    int ra  = (row0 + wr * 16 + g) * 32;                        // rb0 row g
#pragma unroll
    for (int ch = 0; ch < 8; ch++) {
        int ai = ch * 4 + tg;
        uint4 a0  = A4[ra + ai];             // rb0 row g
        uint4 a08 = A4[ra + 8 * 32 + ai];    // rb0 row g+8
        uint4 a1  = A4[ra + 64 * 32 + ai];   // rb1 row g (+64)
        uint4 a18 = A4[ra + 72 * 32 + ai];   // rb1 row g+8
#pragma unroll
        for (int sub = 0; sub < 4; sub++) {
            uint4 bf = B4[(((wh * 8 + ch) * 4 + sub) * 32) + lane];
            mmabf(c[0][sub], a0.x, a08.x, a0.y, a08.y, bf.x, bf.y);
            mmabf(c[0][sub], a0.x, a08.x, a0.y, a08.y, bf.z, bf.w);
            mmabf(c[0][sub], a0.z, a08.z, a0.w, a08.w, bf.x, bf.y);
            mmabf(c[1][sub], a1.x, a18.x, a1.y, a18.y, bf.x, bf.y);
            mmabf(c[1][sub], a1.x, a18.x, a1.y, a18.y, bf.z, bf.w);
            mmabf(c[1][sub], a1.z, a18.z, a1.w, a18.w, bf.x, bf.y);
        }
    }

    // ---- store with bias ----
#pragma unroll
    for (int rb = 0; rb < 2; rb++) {
        int r0 = row0 + rb * 64 + wr * 16 + g;
        int r1 = r0 + 8;
#pragma unroll
        for (int sub = 0; sub < 4; sub++) {
            int lcol = wh * 32 + sub * 8 + 2 * tg;
            int gcol = nt * 64 + lcol;
            float bv0 = bsrc[cbase + lcol];
            float bv1 = bsrc[cbase + lcol + 1];
            if (r0 < NN) {
                g_xlr[r0 * 256 + gcol]     = c[rb][sub][0] + bv0;
                g_xlr[r0 * 256 + gcol + 1] = c[rb][sub][1] + bv1;
            }
            if (r1 < NN) {
                g_xlr[r1 * 256 + gcol]     = c[rb][sub][2] + bv0;
                g_xlr[r1 * 256 + gcol + 1] = c[rb][sub][3] + bv1;
            }
        }
    }
}

// ---------------- fused node kernel: GATv2 + FiLM + LN + GELU + residual (+ bf16 conv) ----
// 2-edge unroll with two independent online-softmax states (exact merge at end):
// doubles gather MLP and halves the serial accumulate chain.
__global__ void k_node(const float* __restrict__ att, const float* __restrict__ We,
                       const float* __restrict__ bo,  const float* __restrict__ lng,
                       const float* __restrict__ lnb, int doconv) {
    int w = (blockIdx.x * blockDim.x + threadIdx.x) >> 5;
    int lane = threadIdx.x & 31;
    if (w >= NN) return;
    int v = w;
    int c0 = lane * 4;
    float4 attv, we0, we1, we2, we3;
    attv.x = att[c0];     attv.y = att[c0 + 1];     attv.z = att[c0 + 2];     attv.w = att[c0 + 3];
    we0.x = We[c0];       we0.y = We[c0 + 1];       we0.z = We[c0 + 2];       we0.w = We[c0 + 3];
    we1.x = We[128 + c0]; we1.y = We[128 + c0 + 1]; we1.z = We[128 + c0 + 2]; we1.w = We[128 + c0 + 3];
    we2.x = We[256 + c0]; we2.y = We[256 + c0 + 1]; we2.z = We[256 + c0 + 2]; we2.w = We[256 + c0 + 3];
    we3.x = We[384 + c0]; we3.y = We[384 + c0 + 1]; we3.z = We[384 + c0 + 2]; we3.w = We[384 + c0 + 3];
    float4 xr = *(const float4*)(g_xlr + v * 256 + 128 + c0);

    float mhA = -1e30f, dhA = 0.0f, mhB = -1e30f, dhB = 0.0f;
    float4 accA = make_float4(0.f, 0.f, 0.f, 0.f);
    float4 accB = make_float4(0.f, 0.f, 0.f, 0.f);
    int beg = g_rowptr[v], end = g_rowptr[v + 1];
    int p = beg;
    for (; p + 1 < end; p += 2) {
        int s0 = g_csrc[p];
        int s1 = g_csrc[p + 1];
        float4 ea0 = g_cea4[p];
        float4 ea1 = g_cea4[p + 1];
        float4 xl0 = *(const float4*)(g_xlr + s0 * 256 + c0);
        float4 xl1 = *(const float4*)(g_xlr + s1 * 256 + c0);
        float4 m0, m1;
        m0.x = xl0.x + xr.x + ea0.x * we0.x + ea0.y * we1.x + ea0.z * we2.x + ea0.w * we3.x;
        m0.y = xl0.y + xr.y + ea0.x * we0.y + ea0.y * we1.y + ea0.z * we2.y + ea0.w * we3.y;
        m0.z = xl0.z + xr.z + ea0.x * we0.z + ea0.y * we1.z + ea0.z * we2.z + ea0.w * we3.z;
        m0.w = xl0.w + xr.w + ea0.x * we0.w + ea0.y * we1.w + ea0.z * we2.w + ea0.w * we3.w;
        m1.x = xl1.x + xr.x + ea1.x * we0.x + ea1.y * we1.x + ea1.z * we2.x + ea1.w * we3.x;
        m1.y = xl1.y + xr.y + ea1.x * we0.y + ea1.y * we1.y + ea1.z * we2.y + ea1.w * we3.y;
        m1.z = xl1.z + xr.z + ea1.x * we0.z + ea1.y * we1.z + ea1.z * we2.z + ea1.w * we3.z;
        m1.w = xl1.w + xr.w + ea1.x * we0.w + ea1.y * we1.w + ea1.z * we2.w + ea1.w * we3.w;
        m0.x = m0.x > 0.f ? m0.x : 0.2f * m0.x;
        m0.y = m0.y > 0.f ? m0.y : 0.2f * m0.y;
        m0.z = m0.z > 0.f ? m0.z : 0.2f * m0.z;
        m0.w = m0.w > 0.f ? m0.w : 0.2f * m0.w;
        m1.x = m1.x > 0.f ? m1.x : 0.2f * m1.x;
        m1.y = m1.y > 0.f ? m1.y : 0.2f * m1.y;
        m1.z = m1.z > 0.f ? m1.z : 0.2f * m1.z;
        m1.w = m1.w > 0.f ? m1.w : 0.2f * m1.w;
        float ap0 = m0.x * attv.x + m0.y * attv.y + m0.z * attv.z + m0.w * attv.w;
        float ap1 = m1.x * attv.x + m1.y * attv.y + m1.z * attv.z + m1.w * attv.w;
        ap0 += __shfl_xor_sync(0xffffffffu, ap0, 1);
        ap1 += __shfl_xor_sync(0xffffffffu, ap1, 1);
        ap0 += __shfl_xor_sync(0xffffffffu, ap0, 2);
        ap1 += __shfl_xor_sync(0xffffffffu, ap1, 2);
        ap0 += __shfl_xor_sync(0xffffffffu, ap0, 4);
        ap1 += __shfl_xor_sync(0xffffffffu, ap1, 4);
        float mnA = fmaxf(mhA, ap0);
        float mnB = fmaxf(mhB, ap1);
        float scA = __expf(mhA - mnA);
        float scB = __expf(mhB - mnB);
        float peA = __expf(ap0 - mnA);
        float peB = __expf(ap1 - mnB);
        dhA = dhA * scA + peA;
        dhB = dhB * scB + peB;
        accA.x = accA.x * scA + peA * xl0.x;
        accB.x = accB.x * scB + peB * xl1.x;
        accA.y = accA.y * scA + peA * xl0.y;
        accB.y = accB.y * scB + peB * xl1.y;
        accA.z = accA.z * scA + peA * xl0.z;
        accB.z = accB.z * scB + peB * xl1.z;
        accA.w = accA.w * scA + peA * xl0.w;
        accB.w = accB.w * scB + peB * xl1.w;
        mhA = mnA; mhB = mnB;
    }
    if (p < end) {
        int s0 = g_csrc[p];
        float4 ea0 = g_cea4[p];
        float4 xl0 = *(const float4*)(g_xlr + s0 * 256 + c0);
        float4 m0;
        m0.x = xl0.x + xr.x + ea0.x * we0.x + ea0.y * we1.x + ea0.z * we2.x + ea0.w * we3.x;
        m0.y = xl0.y + xr.y + ea0.x * we0.y + ea0.y * we1.y + ea0.z * we2.y + ea0.w * we3.y;
        m0.z = xl0.z + xr.z + ea0.x * we0.z + ea0.y * we1.z + ea0.z * we2.z + ea0.w * we3.z;
        m0.w = xl0.w + xr.w + ea0.x * we0.w + ea0.y * we1.w + ea0.z * we2.w + ea0.w * we3.w;
        m0.x = m0.x > 0.f ? m0.x : 0.2f * m0.x;
        m0.y = m0.y > 0.f ? m0.y : 0.2f * m0.y;
        m0.z = m0.z > 0.f ? m0.z : 0.2f * m0.z;
        m0.w = m0.w > 0.f ? m0.w : 0.2f * m0.w;
        float ap0 = m0.x * attv.x + m0.y * attv.y + m0.z * attv.z + m0.w * attv.w;
        ap0 += __shfl_xor_sync(0xffffffffu, ap0, 1);
        ap0 += __shfl_xor_sync(0xffffffffu, ap0, 2);
        ap0 += __shfl_xor_sync(0xffffffffu, ap0, 4);
        float mnA = fmaxf(mhA, ap0);
        float scA = __expf(mhA - mnA);
        float peA = __expf(ap0 - mnA);
        dhA = dhA * scA + peA;
        accA.x = accA.x * scA + peA * xl0.x;
        accA.y = accA.y * scA + peA * xl0.y;
        accA.z = accA.z * scA + peA * xl0.z;
        accA.w = accA.w * scA + peA * xl0.w;
        mhA = mnA;
    }
    // exact merge of the two softmax states
    float mh = fmaxf(mhA, mhB);
    float sA = __expf(mhA - mh);
    float sB = __expf(mhB - mh);
    float dh = dhA * sA + dhB * sB;
    float4 acc;
    acc.x = accA.x * sA + accB.x * sB;
    acc.y = accA.y * sA + accB.y * sB;
    acc.z = accA.z * sA + accB.z * sB;
    acc.w = accA.w * sA + accB.w * sB;

    float rd = 1.0f / dh;
    float4 f;
    f.x = g_gamma[c0 + 0] * (acc.x * rd + bo[c0 + 0]) + g_beta[c0 + 0];
    f.y = g_gamma[c0 + 1] * (acc.y * rd + bo[c0 + 1]) + g_beta[c0 + 1];
    f.z = g_gamma[c0 + 2] * (acc.z * rd + bo[c0 + 2]) + g_beta[c0 + 2];
    f.w = g_gamma[c0 + 3] * (acc.w * rd + bo[c0 + 3]) + g_beta[c0 + 3];
    float S  = f.x + f.y + f.z + f.w;
    float S2 = f.x * f.x + f.y * f.y + f.z * f.z + f.w * f.w;
#pragma unroll
    for (int o = 16; o; o >>= 1) {
        S  += __shfl_xor_sync(0xffffffffu, S,  o);
        S2 += __shfl_xor_sync(0xffffffffu, S2, o);
    }
    float mean = S * (1.0f / HID);
    float var  = S2 * (1.0f / HID) - mean * mean;
    float rstd = rsqrtf(var + 1e-5f);
    float4 hold = *(const float4*)(g_h + v * HID + c0);
    float4 hnew;
    hnew.x = gelu_exact((f.x - mean) * rstd * lng[c0 + 0] + lnb[c0 + 0]) + hold.x;
    hnew.y = gelu_exact((f.y - mean) * rstd * lng[c0 + 1] + lnb[c0 + 1]) + hold.y;
    hnew.z = gelu_exact((f.z - mean) * rstd * lng[c0 + 2] + lnb[c0 + 2]) + hold.z;
    hnew.w = gelu_exact((f.w - mean) * rstd * lng[c0 + 3] + lnb[c0 + 3]) + hold.w;
    *(float4*)(g_h + v * HID + c0) = hnew;
    if (doconv) {
        store_ap(v, c0 + 0, hnew.x);
        store_ap(v, c0 + 1, hnew.y);
        store_ap(v, c0 + 2, hnew.z);
        store_ap(v, c0 + 3, hnew.w);
    }
}

// ---------------- decoder ----------------
__global__ void k_dec(const float* __restrict__ x,
                      const float* __restrict__ W1, const float* __restrict__ b1,
                      const float* __restrict__ W2, const float* __restrict__ b2,
                      float* __restrict__ out) {
    __shared__ float W1s[HID * 64];
    __shared__ float b1s[64];
    __shared__ float W2s[128];
    __shared__ float b2s[2];
    __shared__ float hrow[8][HID];
    __shared__ float hmid[8][64];
    int tid = threadIdx.x;                      // 256
    for (int i = tid; i < HID * 64; i += 256) W1s[i] = W1[i];
    if (tid < 64)  b1s[tid] = b1[tid];
    if (tid < 128) W2s[tid] = W2[tid];
    if (tid < 2)   b2s[tid] = b2[tid];
    __syncthreads();
    int wi = tid >> 5, lane = tid & 31;
    int v = blockIdx.x * 8 + wi;
    if (v >= NN) return;
    {
        float4 hv = ((const float4*)(g_h + v * HID))[lane];
        hrow[wi][lane * 4 + 0] = hv.x; hrow[wi][lane * 4 + 1] = hv.y;
        hrow[wi][lane * 4 + 2] = hv.z; hrow[wi][lane * 4 + 3] = hv.w;
    }
    __syncwarp();
#pragma unroll
    for (int cc = lane; cc < 64; cc += 32) {
        float s = b1s[cc];
#pragma unroll 8
        for (int k = 0; k < HID; k++) s += hrow[wi][k] * W1s[k * 64 + cc];
        hmid[wi][cc] = gelu_exact(s);
    }
    __syncwarp();
    float p0 = hmid[wi][lane] * W2s[lane * 2]     + hmid[wi][lane + 32] * W2s[(lane + 32) * 2];
    float p1 = hmid[wi][lane] * W2s[lane * 2 + 1] + hmid[wi][lane + 32] * W2s[(lane + 32) * 2 + 1];
#pragma unroll
    for (int o = 16; o; o >>= 1) {
        p0 += __shfl_xor_sync(0xffffffffu, p0, o);
        p1 += __shfl_xor_sync(0xffffffffu, p1, o);
    }
    if (lane == 0) {
        float d0 = p0 + b2s[0], d1 = p1 + b2s[1];
        d0 = fminf(fmaxf(d0, -50.0f), 50.0f);
        d1 = fminf(fmaxf(d1, -50.0f), 50.0f);
        float mm = g_mask[v];
        d0 *= mm; d1 *= mm;
        out[v * 2 + 0] = x[v * 6 + 0] + d0;
        out[v * 2 + 1] = x[v * 6 + 1] + d1;
        out[NN * 2 + v * 2 + 0] = d0;
        out[NN * 2 + v * 2 + 1] = d1;
    }
}

// ---------------- launch ----------------
// Profiler lands on launch index 3 -> k_gemm_tc5 there.
extern "C" void kernel_launch(void* const* d_in, const int* in_sizes, int n_in,
                              void* d_out, int out_size) {
    const float* x    = (const float*)d_in[0];
    const void*  ei   = d_in[1];
    const float* ea   = (const float*)d_in[2];
    const float* tmp  = (const float*)d_in[3];
    const void*  msk  = d_in[4];
    const float* encW = (const float*)d_in[5];
    const float* encb = (const float*)d_in[6];
    const float* enlg = (const float*)d_in[7];
    const float* enlb = (const float*)d_in[8];
    const float* fW1  = (const float*)d_in[9];
    const float* fb1  = (const float*)d_in[10];
    const float* fW2  = (const float*)d_in[11];
    const float* fb2  = (const float*)d_in[12];
    const float* Wl   = (const float*)d_in[13];
    const float* bl   = (const float*)d_in[14];
    const float* Wr   = (const float*)d_in[15];
    const float* br   = (const float*)d_in[16];
    const float* att  = (const float*)d_in[17];
    const float* We   = (const float*)d_in[18];
    const float* bo   = (const float*)d_in[19];
    const float* lng  = (const float*)d_in[20];
    const float* lnb  = (const float*)d_in[21];
    const float* dW1  = (const float*)d_in[22];
    const float* db1  = (const float*)d_in[23];
    const float* dW2  = (const float*)d_in[24];
    const float* db2  = (const float*)d_in[25];
    float* out = (float*)d_out;

    const int GEMM_GRID = (NPAD / 128) * 4;       // 1564

    k_enc<<<NN, 128>>>(x, encW, encb, enlg, enlb);                    // 0
    k_convB_all<<<512, 256>>>(Wl, Wr);                                // 1
    k_pre0<<<1, 64>>>(ei, msk);                                       // 2
    k_gemm_tc5<<<GEMM_GRID, 256>>>(bl, br, 0);                        // 3 <- profiled
    k_film<<<1, 256>>>(tmp, fW1, fb1, fW2, fb2);                      // 4
    k_pre1<<<(EE + 255) / 256, 256>>>(ei, msk);                       // 5
    k_hist<<<(EE + 255) / 256, 256>>>(ea);                            // 6
    k_scan<<<1, 1024>>>();                                            // 7
    k_scatter_self<<<(EE + NN + 255) / 256, 256>>>(ea);               // 8
    k_node<<<(NN + 7) / 8, 256>>>(att, We, bo, lng, lnb, 1);          // 9

    for (int i = 1; i < 4; i++) {
        k_gemm_tc5<<<GEMM_GRID, 256>>>(bl + i * HID, br + i * HID, i);
        k_node<<<(NN + 7) / 8, 256>>>(att + i * HID, We + i * 4 * HID,
                                      bo + i * HID, lng + i * HID, lnb + i * HID,
                                      (i < 3) ? 1 : 0);
    }
    k_dec<<<(NN + 7) / 8, 256>>>(x, dW1, db1, dW2, db2, out);
}